// round 4
// baseline (speedup 1.0000x reference)
#include <cuda_runtime.h>
#include <cstdint>

#define NFFT 16384
#define DIML 8192
#define DIMD 1024
#define NT   1024

// per-stage twiddle table offsets in smem (float2 units)
#define OT4096 0
#define OT1024 4096
#define OT256  5120
#define OT64   5376
#define OT16   5440
#define OT4    5456
#define NTW    5460

// conflict-killing swizzle: XOR low 4 bits with bits[7:4] (self-inverse)
#define SWZ(i) ((i) ^ (((i) >> 4) & 15))

// ---------------- device scratch ----------------
__device__ float2 g_twst[NTW];
__device__ float4 g_H [(size_t)DIMD * NFFT / 2];   // per-CTA H spectrum spill (L2-resident live set)
__device__ float2 g_xt[(size_t)DIMD * DIML];       // transposed x, batches packed
__device__ float  g_ht[(size_t)DIMD * DIML];       // transposed h

__device__ __forceinline__ float2 cmul(float2 a, float2 b) {
    return make_float2(a.x * b.x - a.y * b.y, a.x * b.y + a.y * b.x);
}
__device__ __forceinline__ float2 cadd(float2 a, float2 b) { return make_float2(a.x + b.x, a.y + b.y); }
__device__ __forceinline__ float2 csub(float2 a, float2 b) { return make_float2(a.x - b.x, a.y - b.y); }

// DIF forward radix-4 butterfly (in place)
__device__ __forceinline__ void bfly(float2& a, float2& b, float2& c, float2& d) {
    float2 t0 = cadd(a, c), t1 = csub(a, c), t2 = cadd(b, d), t3 = csub(b, d);
    a = cadd(t0, t2);
    b = make_float2(t1.x + t3.y, t1.y - t3.x);
    c = csub(t0, t2);
    d = make_float2(t1.x - t3.y, t1.y + t3.x);
}
// inverse radix-4 butterfly (unnormalized)
__device__ __forceinline__ void ibfly(float2& a, float2& b, float2& c, float2& d) {
    float2 u0 = cadd(a, c), u1 = csub(a, c), u2 = cadd(b, d), u3 = csub(b, d);
    a = cadd(u0, u2);
    b = make_float2(u1.x - u3.y, u1.y + u3.x);
    c = csub(u0, u2);
    d = make_float2(u1.x + u3.y, u1.y - u3.x);
}
__device__ __forceinline__ void tw3(float2& b, float2& c, float2& d, float2 w) {
    float2 w2 = cmul(w, w), w3 = cmul(w, w2);
    b = cmul(b, w); c = cmul(c, w2); d = cmul(d, w3);
}
__device__ __forceinline__ void itw3(float2& b, float2& c, float2& d, float2 w) {
    float2 wc = make_float2(w.x, -w.y);
    float2 w2 = cmul(wc, wc), w3 = cmul(wc, w2);
    b = cmul(b, wc); c = cmul(c, w2); d = cmul(d, w3);
}

// ---------------- twiddle init ----------------
__global__ void twiddle_kernel() {
    const int offs[6] = {OT4096, OT1024, OT256, OT64, OT16, OT4};
    const int ms[6]   = {4096, 1024, 256, 64, 16, 4};
    int si = blockIdx.y;
    int m  = ms[si];
    int r  = blockIdx.x * 256 + threadIdx.x;
    if (r < m) {
        float s, c;
        sincospif(0.5f * (float)r / (float)m, &s, &c);
        g_twst[offs[si] + r] = make_float2(c, -s);
    }
}

// ---------------- transposes ----------------
__global__ __launch_bounds__(256)
void transpose_x_kernel(const float* __restrict__ x) {
    __shared__ float2 tile[32][33];
    const int d0 = blockIdx.x * 32, n0 = blockIdx.y * 32;
    for (int i = threadIdx.y; i < 32; i += 8) {
        const size_t base = (size_t)(n0 + i) * DIMD + d0 + threadIdx.x;
        tile[i][threadIdx.x] = make_float2(x[base], x[base + (size_t)DIML * DIMD]);
    }
    __syncthreads();
    for (int i = threadIdx.y; i < 32; i += 8)
        g_xt[(size_t)(d0 + i) * DIML + n0 + threadIdx.x] = tile[threadIdx.x][i];
}

__global__ __launch_bounds__(256)
void transpose_h_kernel(const float* __restrict__ h) {
    __shared__ float tile[32][33];
    const int d0 = blockIdx.x * 32, n0 = blockIdx.y * 32;
    for (int i = threadIdx.y; i < 32; i += 8)
        tile[i][threadIdx.x] = h[(size_t)(n0 + i) * DIMD + d0 + threadIdx.x];
    __syncthreads();
    for (int i = threadIdx.y; i < 32; i += 8)
        g_ht[(size_t)(d0 + i) * DIML + n0 + threadIdx.x] = tile[threadIdx.x][i];
}

// ================= forward pass helpers =====================================

__device__ __forceinline__ void passA_fwd(float2 v[4][4], const float2* sT, int t) {
    #pragma unroll
    for (int b = 0; b < 4; b++) {
        bfly(v[0][b], v[1][b], v[2][b], v[3][b]);
        tw3(v[1][b], v[2][b], v[3][b], sT[OT4096 + t + 1024 * b]);
    }
    float2 w = sT[OT1024 + t];
    #pragma unroll
    for (int a = 0; a < 4; a++) {
        bfly(v[a][0], v[a][1], v[a][2], v[a][3]);
        tw3(v[a][1], v[a][2], v[a][3], w);
    }
}

__device__ __forceinline__ void passB_fwd(float2* sA, const float2* sT, int t) {
    const int u = t >> 6, rp = t & 63;
    const int base = u * 1024 + rp;
    float2 v[4][4];
    #pragma unroll
    for (int a = 0; a < 4; a++)
        #pragma unroll
        for (int b = 0; b < 4; b++)
            v[a][b] = sA[SWZ(base + 64 * b + 256 * a)];
    #pragma unroll
    for (int b = 0; b < 4; b++) {
        bfly(v[0][b], v[1][b], v[2][b], v[3][b]);
        tw3(v[1][b], v[2][b], v[3][b], sT[OT256 + rp + 64 * b]);
    }
    float2 w = sT[OT64 + rp];
    #pragma unroll
    for (int a = 0; a < 4; a++) {
        bfly(v[a][0], v[a][1], v[a][2], v[a][3]);
        tw3(v[a][1], v[a][2], v[a][3], w);
    }
    #pragma unroll
    for (int a = 0; a < 4; a++)
        #pragma unroll
        for (int b = 0; b < 4; b++)
            sA[SWZ(base + 64 * b + 256 * a)] = v[a][b];
}

__device__ __forceinline__ void passC_fwd(float2* sA, const float2* sT, int t) {
    const int rq = t & 15, qb = t >> 4;
    const int base = qb * 64 + rq;
    float2 v[4][4];
    #pragma unroll
    for (int s = 0; s < 4; s++)
        #pragma unroll
        for (int a = 0; a < 4; a++)
            v[s][a] = sA[SWZ(base + 4096 * s + 16 * a)];
    float2 w = sT[OT16 + rq];
    #pragma unroll
    for (int s = 0; s < 4; s++) {
        bfly(v[s][0], v[s][1], v[s][2], v[s][3]);
        tw3(v[s][1], v[s][2], v[s][3], w);
    }
    #pragma unroll
    for (int s = 0; s < 4; s++)
        #pragma unroll
        for (int a = 0; a < 4; a++)
            sA[SWZ(base + 4096 * s + 16 * a)] = v[s][a];
}

__device__ __forceinline__ void passD_fwd(float2 u16[16], const float2* sT) {
    #pragma unroll
    for (int r = 0; r < 4; r++) {
        bfly(u16[r], u16[r + 4], u16[r + 8], u16[r + 12]);
        tw3(u16[r + 4], u16[r + 8], u16[r + 12], sT[OT4 + r]);
    }
    #pragma unroll
    for (int g = 0; g < 4; g++)
        bfly(u16[4 * g], u16[4 * g + 1], u16[4 * g + 2], u16[4 * g + 3]);
}

// runs a full forward FFT over sA given v[4][4] already holding pass-A input,
// leaving pass-D output (16 spectrum values) in u16
__device__ __forceinline__ void fwd_to_regs(float2 v[4][4], float2 u16[16],
                                            float2* sA, const float2* sT, int t) {
    passA_fwd(v, sT, t);
    #pragma unroll
    for (int a = 0; a < 4; a++)
        #pragma unroll
        for (int b = 0; b < 4; b++)
            sA[SWZ(t + 1024 * b + 4096 * a)] = v[a][b];
    __syncthreads();
    passB_fwd(sA, sT, t);
    __syncthreads();
    passC_fwd(sA, sT, t);
    __syncthreads();
    #pragma unroll
    for (int j = 0; j < 16; j++) u16[j] = sA[SWZ(16 * t + j)];
    passD_fwd(u16, sT);
}

// ================= fused conv: h-FFT + x-FFT + multiply + inverse ===========
__global__ __launch_bounds__(NT, 1)
void fft_conv_fused_kernel(const float* __restrict__ bias, float* __restrict__ y) {
    extern __shared__ float2 sm[];
    float2* sA = sm;
    float2* sT = sm + NFFT;
    const int t = threadIdx.x, d = blockIdx.x;

    for (int j = t; j < NTW; j += NT) sT[j] = g_twst[j];

    // ---------------- h forward FFT ----------------
    {
        const float* hp = g_ht + (size_t)d * DIML;
        float2 v[4][4];
        #pragma unroll
        for (int a = 0; a < 4; a++)
            #pragma unroll
            for (int b = 0; b < 4; b++)
                v[a][b] = (a < 2) ? make_float2(hp[t + 1024 * b + 4096 * a], 0.0f)
                                  : make_float2(0.0f, 0.0f);
        __syncthreads();                     // twiddle tables visible
        float2 u16[16];
        fwd_to_regs(v, u16, sA, sT, t);
        // spill H spectrum (same thread reloads it later -> no fence needed)
        float4* Hd = g_H + (size_t)d * (NFFT / 2) + 8 * t;
        #pragma unroll
        for (int p = 0; p < 8; p++)
            Hd[p] = make_float4(u16[2 * p].x, u16[2 * p].y,
                                u16[2 * p + 1].x, u16[2 * p + 1].y);
    }
    __syncthreads();                         // everyone done reading sA (pass D)

    // ---------------- x forward FFT ----------------
    {
        const float2* xp = g_xt + (size_t)d * DIML;
        float2 v[4][4];
        #pragma unroll
        for (int a = 0; a < 4; a++)
            #pragma unroll
            for (int b = 0; b < 4; b++)
                v[a][b] = (a < 2) ? xp[t + 1024 * b + 4096 * a] : make_float2(0.0f, 0.0f);
        float2 u16[16];
        fwd_to_regs(v, u16, sA, sT, t);

        // multiply by H (L2-resident reload), inverse stages 1 then 4
        const float4* Hd = g_H + (size_t)d * (NFFT / 2) + 8 * t;
        #pragma unroll
        for (int p = 0; p < 8; p++) {
            float4 hv = Hd[p];
            u16[2 * p]     = cmul(u16[2 * p],     make_float2(hv.x, hv.y));
            u16[2 * p + 1] = cmul(u16[2 * p + 1], make_float2(hv.z, hv.w));
        }
        #pragma unroll
        for (int g = 0; g < 4; g++)
            ibfly(u16[4 * g], u16[4 * g + 1], u16[4 * g + 2], u16[4 * g + 3]);
        #pragma unroll
        for (int r = 0; r < 4; r++) {
            itw3(u16[r + 4], u16[r + 8], u16[r + 12], sT[OT4 + r]);
            ibfly(u16[r], u16[r + 4], u16[r + 8], u16[r + 12]);
        }
        #pragma unroll
        for (int j = 0; j < 16; j++) sA[SWZ(16 * t + j)] = u16[j];
    }
    __syncthreads();

    // ---- pass C': inverse stage 16 ----
    {
        const int rq = t & 15, qb = t >> 4;
        const int base = qb * 64 + rq;
        float2 w = sT[OT16 + rq];
        float2 vc[4][4];
        #pragma unroll
        for (int s = 0; s < 4; s++)
            #pragma unroll
            for (int a = 0; a < 4; a++)
                vc[s][a] = sA[SWZ(base + 4096 * s + 16 * a)];
        #pragma unroll
        for (int s = 0; s < 4; s++) {
            itw3(vc[s][1], vc[s][2], vc[s][3], w);
            ibfly(vc[s][0], vc[s][1], vc[s][2], vc[s][3]);
        }
        #pragma unroll
        for (int s = 0; s < 4; s++)
            #pragma unroll
            for (int a = 0; a < 4; a++)
                sA[SWZ(base + 4096 * s + 16 * a)] = vc[s][a];
    }
    __syncthreads();

    // ---- pass B': inverse stages 64 then 256 ----
    {
        const int u = t >> 6, rp = t & 63;
        const int base = u * 1024 + rp;
        float2 vb[4][4];
        #pragma unroll
        for (int a = 0; a < 4; a++)
            #pragma unroll
            for (int b = 0; b < 4; b++)
                vb[a][b] = sA[SWZ(base + 64 * b + 256 * a)];
        float2 w64 = sT[OT64 + rp];
        #pragma unroll
        for (int a = 0; a < 4; a++) {
            itw3(vb[a][1], vb[a][2], vb[a][3], w64);
            ibfly(vb[a][0], vb[a][1], vb[a][2], vb[a][3]);
        }
        #pragma unroll
        for (int b = 0; b < 4; b++) {
            itw3(vb[1][b], vb[2][b], vb[3][b], sT[OT256 + rp + 64 * b]);
            ibfly(vb[0][b], vb[1][b], vb[2][b], vb[3][b]);
        }
        #pragma unroll
        for (int a = 0; a < 4; a++)
            #pragma unroll
            for (int b = 0; b < 4; b++)
                sA[SWZ(base + 64 * b + 256 * a)] = vb[a][b];
    }
    __syncthreads();

    // ---- pass A': inverse stages 1024 then 4096, scale + bias + direct store
    {
        float2 va[4][4];
        #pragma unroll
        for (int a = 0; a < 4; a++)
            #pragma unroll
            for (int b = 0; b < 4; b++)
                va[a][b] = sA[SWZ(t + 1024 * b + 4096 * a)];
        float2 w1024 = sT[OT1024 + t];
        #pragma unroll
        for (int a = 0; a < 4; a++) {
            itw3(va[a][1], va[a][2], va[a][3], w1024);
            ibfly(va[a][0], va[a][1], va[a][2], va[a][3]);
        }
        #pragma unroll
        for (int b = 0; b < 4; b++) {
            itw3(va[1][b], va[2][b], va[3][b], sT[OT4096 + t + 1024 * b]);
            ibfly(va[0][b], va[1][b], va[2][b], va[3][b]);
        }
        const float scale = 1.0f / (float)NFFT;
        const float bv = __ldg(&bias[d]);
        // y[b][n][d], n = t + 1024*bb + 4096*a  (only a<2 are real samples)
        #pragma unroll
        for (int a = 0; a < 2; a++)
            #pragma unroll
            for (int bb = 0; bb < 4; bb++) {
                float2 r = va[a][bb];
                const size_t n = (size_t)(t + 1024 * bb + 4096 * a);
                y[n * DIMD + d]                          = fmaf(r.x, scale, bv);
                y[((size_t)DIML + n) * DIMD + d]         = fmaf(r.y, scale, bv);
            }
    }
}

// ---------------------------------------------------------------------------
extern "C" void kernel_launch(void* const* d_in, const int* in_sizes, int n_in,
                              void* d_out, int out_size) {
    const float* x    = (const float*)d_in[0];
    const float* h    = (const float*)d_in[1];
    const float* bias = (const float*)d_in[2];
    float* y = (float*)d_out;

    const int smem = (NFFT + NTW) * sizeof(float2);  // ~171 KB
    cudaFuncSetAttribute(fft_conv_fused_kernel,
                         cudaFuncAttributeMaxDynamicSharedMemorySize, smem);

    twiddle_kernel<<<dim3(16, 6), 256>>>();
    transpose_x_kernel<<<dim3(DIMD / 32, DIML / 32), dim3(32, 8)>>>(x);
    transpose_h_kernel<<<dim3(DIMD / 32, DIML / 32), dim3(32, 8)>>>(h);
    fft_conv_fused_kernel<<<DIMD, NT, smem>>>(bias, y);
}

// round 5
// speedup vs baseline: 1.1617x; 1.1617x over previous
#include <cuda_runtime.h>
#include <cstdint>

#define NFFT 16384
#define DIML 8192
#define DIMD 1024
#define NT   1024

// per-stage twiddle table offsets in smem (float2 units)
#define OT4096 0
#define OT1024 4096
#define OT256  5120
#define OT64   5376
#define OT16   5440
#define OT4    5456
#define NTW    5460

// conflict-killing swizzle: XOR low 4 bits with bits[7:4] (self-inverse)
#define SWZ(i) ((i) ^ (((i) >> 4) & 15))

// ---------------- device scratch ----------------
__device__ float2 g_twst[NTW];
__device__ float4 g_H [(size_t)DIMD * NFFT / 2];   // spectrum of h, pass-D layout
__device__ float2 g_xt[(size_t)DIMD * DIML];       // transposed x, batches packed
__device__ float  g_ht[(size_t)DIMD * DIML];       // transposed h
__device__ float2 g_ys[(size_t)DIMD * DIML];       // transposed scaled output

// ---------------- packed f32x2 complex add/sub (sm_103a) ----------------
__device__ __forceinline__ float2 cadd(float2 a, float2 b) {
    unsigned long long ua, ub, ur;
    asm("mov.b64 %0, {%1, %2};" : "=l"(ua) : "f"(a.x), "f"(a.y));
    asm("mov.b64 %0, {%1, %2};" : "=l"(ub) : "f"(b.x), "f"(b.y));
    asm("add.rn.f32x2 %0, %1, %2;" : "=l"(ur) : "l"(ua), "l"(ub));
    float2 r;
    asm("mov.b64 {%0, %1}, %2;" : "=f"(r.x), "=f"(r.y) : "l"(ur));
    return r;
}
__device__ __forceinline__ float2 csub(float2 a, float2 b) {
    unsigned long long ua, ub, ur;
    asm("mov.b64 %0, {%1, %2};" : "=l"(ua) : "f"(a.x), "f"(a.y));
    asm("mov.b64 %0, {%1, %2};" : "=l"(ub) : "f"(b.x), "f"(b.y));
    asm("sub.rn.f32x2 %0, %1, %2;" : "=l"(ur) : "l"(ua), "l"(ub));
    float2 r;
    asm("mov.b64 {%0, %1}, %2;" : "=f"(r.x), "=f"(r.y) : "l"(ur));
    return r;
}
__device__ __forceinline__ float2 cmul(float2 a, float2 b) {
    return make_float2(a.x * b.x - a.y * b.y, a.x * b.y + a.y * b.x);
}

// DIF forward radix-4 butterfly (in place), packed adds
__device__ __forceinline__ void bfly(float2& a, float2& b, float2& c, float2& d) {
    float2 t0 = cadd(a, c), t1 = csub(a, c), t2 = cadd(b, d), t3 = csub(b, d);
    float2 t3s = make_float2(t3.y, -t3.x);     // -i * t3
    a = cadd(t0, t2);
    c = csub(t0, t2);
    b = cadd(t1, t3s);
    d = csub(t1, t3s);
}
// inverse radix-4 butterfly (unnormalized)
__device__ __forceinline__ void ibfly(float2& a, float2& b, float2& c, float2& d) {
    float2 u0 = cadd(a, c), u1 = csub(a, c), u2 = cadd(b, d), u3 = csub(b, d);
    float2 u3s = make_float2(u3.y, -u3.x);
    a = cadd(u0, u2);
    c = csub(u0, u2);
    b = csub(u1, u3s);
    d = cadd(u1, u3s);
}
// apply given powers
__device__ __forceinline__ void tw3w(float2& b, float2& c, float2& d,
                                     float2 w1, float2 w2, float2 w3) {
    b = cmul(b, w1); c = cmul(c, w2); d = cmul(d, w3);
}
// compute powers then apply (non-shared twiddle)
__device__ __forceinline__ void tw3(float2& b, float2& c, float2& d, float2 w) {
    float2 w2 = cmul(w, w), w3 = cmul(w, w2);
    tw3w(b, c, d, w, w2, w3);
}
__device__ __forceinline__ void itw3(float2& b, float2& c, float2& d, float2 w) {
    float2 wc = make_float2(w.x, -w.y);
    float2 w2 = cmul(wc, wc), w3 = cmul(wc, w2);
    tw3w(b, c, d, wc, w2, w3);
}

// ---------------- twiddle init ----------------
__global__ void twiddle_kernel() {
    const int offs[6] = {OT4096, OT1024, OT256, OT64, OT16, OT4};
    const int ms[6]   = {4096, 1024, 256, 64, 16, 4};
    int si = blockIdx.y;
    int m  = ms[si];
    int r  = blockIdx.x * 256 + threadIdx.x;
    if (r < m) {
        float s, c;
        sincospif(0.5f * (float)r / (float)m, &s, &c);
        g_twst[offs[si] + r] = make_float2(c, -s);
    }
}

// ---------------- transposes ----------------
__global__ __launch_bounds__(256)
void transpose_x_kernel(const float* __restrict__ x) {
    __shared__ float2 tile[32][33];
    const int d0 = blockIdx.x * 32, n0 = blockIdx.y * 32;
    for (int i = threadIdx.y; i < 32; i += 8) {
        const size_t base = (size_t)(n0 + i) * DIMD + d0 + threadIdx.x;
        tile[i][threadIdx.x] = make_float2(x[base], x[base + (size_t)DIML * DIMD]);
    }
    __syncthreads();
    for (int i = threadIdx.y; i < 32; i += 8)
        g_xt[(size_t)(d0 + i) * DIML + n0 + threadIdx.x] = tile[threadIdx.x][i];
}

__global__ __launch_bounds__(256)
void transpose_h_kernel(const float* __restrict__ h) {
    __shared__ float tile[32][33];
    const int d0 = blockIdx.x * 32, n0 = blockIdx.y * 32;
    for (int i = threadIdx.y; i < 32; i += 8)
        tile[i][threadIdx.x] = h[(size_t)(n0 + i) * DIMD + d0 + threadIdx.x];
    __syncthreads();
    for (int i = threadIdx.y; i < 32; i += 8)
        g_ht[(size_t)(d0 + i) * DIML + n0 + threadIdx.x] = tile[threadIdx.x][i];
}

__global__ __launch_bounds__(256)
void transpose_out_kernel(const float* __restrict__ bias, float* __restrict__ y) {
    __shared__ float2 tile[32][33];
    const int n0 = blockIdx.x * 32, d0 = blockIdx.y * 32;
    for (int i = threadIdx.y; i < 32; i += 8)
        tile[i][threadIdx.x] = g_ys[(size_t)(d0 + i) * DIML + n0 + threadIdx.x];
    __syncthreads();
    for (int i = threadIdx.y; i < 32; i += 8) {
        const int d = d0 + threadIdx.x;
        const int n = n0 + i;
        const float bv = __ldg(&bias[d]);
        const float2 v = tile[threadIdx.x][i];
        y[(size_t)n * DIMD + d]          = v.x + bv;
        y[(size_t)(DIML + n) * DIMD + d] = v.y + bv;
    }
}

// ================= forward pass helpers =====================================

// Pass A: stages m=4096, m=1024 on v[a][b] (element t+1024b+4096a)
__device__ __forceinline__ void passA_fwd(float2 v[4][4], const float2* sT, int t) {
    #pragma unroll
    for (int b = 0; b < 4; b++) {
        bfly(v[0][b], v[1][b], v[2][b], v[3][b]);
        tw3(v[1][b], v[2][b], v[3][b], sT[OT4096 + t + 1024 * b]);
    }
    float2 w1 = sT[OT1024 + t];
    float2 w2 = cmul(w1, w1), w3 = cmul(w1, w2);
    #pragma unroll
    for (int a = 0; a < 4; a++) {
        bfly(v[a][0], v[a][1], v[a][2], v[a][3]);
        tw3w(v[a][1], v[a][2], v[a][3], w1, w2, w3);
    }
}

// Pass B: stages m=256, m=64. element e(a,b) = u*1024 + rp + 64b + 256a
__device__ __forceinline__ void passB_fwd(float2* sA, const float2* sT, int t) {
    const int u = t >> 6, rp = t & 63;
    const int base = u * 1024 + rp;
    float2 v[4][4];
    #pragma unroll
    for (int a = 0; a < 4; a++)
        #pragma unroll
        for (int b = 0; b < 4; b++)
            v[a][b] = sA[SWZ(base + 64 * b + 256 * a)];
    #pragma unroll
    for (int b = 0; b < 4; b++) {
        bfly(v[0][b], v[1][b], v[2][b], v[3][b]);
        tw3(v[1][b], v[2][b], v[3][b], sT[OT256 + rp + 64 * b]);
    }
    float2 w1 = sT[OT64 + rp];
    float2 w2 = cmul(w1, w1), w3 = cmul(w1, w2);
    #pragma unroll
    for (int a = 0; a < 4; a++) {
        bfly(v[a][0], v[a][1], v[a][2], v[a][3]);
        tw3w(v[a][1], v[a][2], v[a][3], w1, w2, w3);
    }
    #pragma unroll
    for (int a = 0; a < 4; a++)
        #pragma unroll
        for (int b = 0; b < 4; b++)
            sA[SWZ(base + 64 * b + 256 * a)] = v[a][b];
}

// Pass C: stage m=16. element e(s,a) = qb*64 + rq + 4096s + 16a
__device__ __forceinline__ void passC_fwd(float2* sA, const float2* sT, int t) {
    const int rq = t & 15, qb = t >> 4;
    const int base = qb * 64 + rq;
    float2 v[4][4];
    #pragma unroll
    for (int s = 0; s < 4; s++)
        #pragma unroll
        for (int a = 0; a < 4; a++)
            v[s][a] = sA[SWZ(base + 4096 * s + 16 * a)];
    float2 w1 = sT[OT16 + rq];
    float2 w2 = cmul(w1, w1), w3 = cmul(w1, w2);
    #pragma unroll
    for (int s = 0; s < 4; s++) {
        bfly(v[s][0], v[s][1], v[s][2], v[s][3]);
        tw3w(v[s][1], v[s][2], v[s][3], w1, w2, w3);
    }
    #pragma unroll
    for (int s = 0; s < 4; s++)
        #pragma unroll
        for (int a = 0; a < 4; a++)
            sA[SWZ(base + 4096 * s + 16 * a)] = v[s][a];
}

// Pass D forward: stages m=4, m=1 on u16 (elements 16t..16t+15)
__device__ __forceinline__ void passD_fwd(float2 u16[16], const float2* sT) {
    #pragma unroll
    for (int r = 0; r < 4; r++) {
        bfly(u16[r], u16[r + 4], u16[r + 8], u16[r + 12]);
        tw3(u16[r + 4], u16[r + 8], u16[r + 12], sT[OT4 + r]);
    }
    #pragma unroll
    for (int g = 0; g < 4; g++)
        bfly(u16[4 * g], u16[4 * g + 1], u16[4 * g + 2], u16[4 * g + 3]);
}

// ================= FFT of h: forward only, store spectrum ===================
__global__ __launch_bounds__(NT, 1)
void fft_h_kernel() {
    extern __shared__ float2 sm[];
    float2* sA = sm;
    float2* sT = sm + NFFT;
    const int t = threadIdx.x, d = blockIdx.x;

    for (int j = t; j < NTW; j += NT) sT[j] = g_twst[j];

    const float* hp = g_ht + (size_t)d * DIML;
    float2 v[4][4];
    #pragma unroll
    for (int a = 0; a < 4; a++)
        #pragma unroll
        for (int b = 0; b < 4; b++)
            v[a][b] = (a < 2) ? make_float2(hp[t + 1024 * b + 4096 * a], 0.0f)
                              : make_float2(0.0f, 0.0f);
    __syncthreads();                       // twiddle tables visible

    passA_fwd(v, sT, t);
    #pragma unroll
    for (int a = 0; a < 4; a++)
        #pragma unroll
        for (int b = 0; b < 4; b++)
            sA[SWZ(t + 1024 * b + 4096 * a)] = v[a][b];
    __syncthreads();

    passB_fwd(sA, sT, t);
    __syncthreads();
    passC_fwd(sA, sT, t);
    __syncthreads();

    float2 u16[16];
    #pragma unroll
    for (int j = 0; j < 16; j++) u16[j] = sA[SWZ(16 * t + j)];
    passD_fwd(u16, sT);

    float4* Hd = g_H + (size_t)d * (NFFT / 2) + 8 * t;
    #pragma unroll
    for (int p = 0; p < 8; p++)
        Hd[p] = make_float4(u16[2 * p].x, u16[2 * p].y, u16[2 * p + 1].x, u16[2 * p + 1].y);
}

// ================= conv: fwd FFT, multiply, inverse FFT =====================
__global__ __launch_bounds__(NT, 1)
void fft_conv_kernel() {
    extern __shared__ float2 sm[];
    float2* sA = sm;
    float2* sT = sm + NFFT;
    const int t = threadIdx.x, d = blockIdx.x;

    for (int j = t; j < NTW; j += NT) sT[j] = g_twst[j];

    const float2* xp = g_xt + (size_t)d * DIML;
    float2 v[4][4];
    #pragma unroll
    for (int a = 0; a < 4; a++)
        #pragma unroll
        for (int b = 0; b < 4; b++)
            v[a][b] = (a < 2) ? xp[t + 1024 * b + 4096 * a] : make_float2(0.0f, 0.0f);
    __syncthreads();

    passA_fwd(v, sT, t);
    #pragma unroll
    for (int a = 0; a < 4; a++)
        #pragma unroll
        for (int b = 0; b < 4; b++)
            sA[SWZ(t + 1024 * b + 4096 * a)] = v[a][b];
    __syncthreads();

    passB_fwd(sA, sT, t);
    __syncthreads();
    passC_fwd(sA, sT, t);
    __syncthreads();

    // ---- pass D: fwd(4,1) + multiply by H + inv(1,4), all in registers ----
    {
        float2 u16[16];
        #pragma unroll
        for (int j = 0; j < 16; j++) u16[j] = sA[SWZ(16 * t + j)];
        passD_fwd(u16, sT);

        const float4* Hd = g_H + (size_t)d * (NFFT / 2) + 8 * t;
        #pragma unroll
        for (int p = 0; p < 8; p++) {
            float4 hv = __ldg(&Hd[p]);
            u16[2 * p]     = cmul(u16[2 * p],     make_float2(hv.x, hv.y));
            u16[2 * p + 1] = cmul(u16[2 * p + 1], make_float2(hv.z, hv.w));
        }

        #pragma unroll
        for (int g = 0; g < 4; g++)
            ibfly(u16[4 * g], u16[4 * g + 1], u16[4 * g + 2], u16[4 * g + 3]);
        #pragma unroll
        for (int r = 0; r < 4; r++) {
            itw3(u16[r + 4], u16[r + 8], u16[r + 12], sT[OT4 + r]);
            ibfly(u16[r], u16[r + 4], u16[r + 8], u16[r + 12]);
        }
        #pragma unroll
        for (int j = 0; j < 16; j++) sA[SWZ(16 * t + j)] = u16[j];
    }
    __syncthreads();

    // ---- pass C': inverse stage 16 ----
    {
        const int rq = t & 15, qb = t >> 4;
        const int base = qb * 64 + rq;
        float2 w1 = sT[OT16 + rq];
        w1.y = -w1.y;
        float2 w2 = cmul(w1, w1), w3 = cmul(w1, w2);
        float2 vc[4][4];
        #pragma unroll
        for (int s = 0; s < 4; s++)
            #pragma unroll
            for (int a = 0; a < 4; a++)
                vc[s][a] = sA[SWZ(base + 4096 * s + 16 * a)];
        #pragma unroll
        for (int s = 0; s < 4; s++) {
            tw3w(vc[s][1], vc[s][2], vc[s][3], w1, w2, w3);
            ibfly(vc[s][0], vc[s][1], vc[s][2], vc[s][3]);
        }
        #pragma unroll
        for (int s = 0; s < 4; s++)
            #pragma unroll
            for (int a = 0; a < 4; a++)
                sA[SWZ(base + 4096 * s + 16 * a)] = vc[s][a];
    }
    __syncthreads();

    // ---- pass B': inverse stages 64 then 256 ----
    {
        const int u = t >> 6, rp = t & 63;
        const int base = u * 1024 + rp;
        float2 vb[4][4];
        #pragma unroll
        for (int a = 0; a < 4; a++)
            #pragma unroll
            for (int b = 0; b < 4; b++)
                vb[a][b] = sA[SWZ(base + 64 * b + 256 * a)];
        float2 w1 = sT[OT64 + rp];
        w1.y = -w1.y;
        float2 w2 = cmul(w1, w1), w3 = cmul(w1, w2);
        #pragma unroll
        for (int a = 0; a < 4; a++) {
            tw3w(vb[a][1], vb[a][2], vb[a][3], w1, w2, w3);
            ibfly(vb[a][0], vb[a][1], vb[a][2], vb[a][3]);
        }
        #pragma unroll
        for (int b = 0; b < 4; b++) {
            itw3(vb[1][b], vb[2][b], vb[3][b], sT[OT256 + rp + 64 * b]);
            ibfly(vb[0][b], vb[1][b], vb[2][b], vb[3][b]);
        }
        #pragma unroll
        for (int a = 0; a < 4; a++)
            #pragma unroll
            for (int b = 0; b < 4; b++)
                sA[SWZ(base + 64 * b + 256 * a)] = vb[a][b];
    }
    __syncthreads();

    // ---- pass A': inverse stages 1024 then 4096, scale + store ----
    {
        float2 va[4][4];
        #pragma unroll
        for (int a = 0; a < 4; a++)
            #pragma unroll
            for (int b = 0; b < 4; b++)
                va[a][b] = sA[SWZ(t + 1024 * b + 4096 * a)];
        float2 w1 = sT[OT1024 + t];
        w1.y = -w1.y;
        float2 w2 = cmul(w1, w1), w3 = cmul(w1, w2);
        #pragma unroll
        for (int a = 0; a < 4; a++) {
            tw3w(va[a][1], va[a][2], va[a][3], w1, w2, w3);
            ibfly(va[a][0], va[a][1], va[a][2], va[a][3]);
        }
        #pragma unroll
        for (int b = 0; b < 4; b++) {
            itw3(va[1][b], va[2][b], va[3][b], sT[OT4096 + t + 1024 * b]);
            ibfly(va[0][b], va[1][b], va[2][b], va[3][b]);
        }
        const float scale = 1.0f / (float)NFFT;
        float2* yp = g_ys + (size_t)d * DIML;
        #pragma unroll
        for (int a = 0; a < 2; a++)
            #pragma unroll
            for (int b = 0; b < 4; b++) {
                float2 r = va[a][b];
                yp[t + 1024 * b + 4096 * a] = make_float2(r.x * scale, r.y * scale);
            }
    }
}

// ---------------------------------------------------------------------------
extern "C" void kernel_launch(void* const* d_in, const int* in_sizes, int n_in,
                              void* d_out, int out_size) {
    const float* x    = (const float*)d_in[0];
    const float* h    = (const float*)d_in[1];
    const float* bias = (const float*)d_in[2];
    float* y = (float*)d_out;

    const int smem = (NFFT + NTW) * sizeof(float2);  // ~171 KB
    cudaFuncSetAttribute(fft_h_kernel,
                         cudaFuncAttributeMaxDynamicSharedMemorySize, smem);
    cudaFuncSetAttribute(fft_conv_kernel,
                         cudaFuncAttributeMaxDynamicSharedMemorySize, smem);

    twiddle_kernel<<<dim3(16, 6), 256>>>();
    transpose_x_kernel<<<dim3(DIMD / 32, DIML / 32), dim3(32, 8)>>>(x);
    transpose_h_kernel<<<dim3(DIMD / 32, DIML / 32), dim3(32, 8)>>>(h);
    fft_h_kernel<<<DIMD, NT, smem>>>();
    fft_conv_kernel<<<DIMD, NT, smem>>>();
    transpose_out_kernel<<<dim3(DIML / 32, DIMD / 32), dim3(32, 8)>>>(bias, y);
}

// round 6
// speedup vs baseline: 1.2166x; 1.0473x over previous
#include <cuda_runtime.h>
#include <cstdint>

#define NFFT 16384
#define DIML 8192
#define DIMD 1024
#define NT   512        // 512 threads, 32 elements per thread (2 groups of 16)

// per-stage twiddle table offsets in smem (float2 units)
#define OT4096 0
#define OT1024 4096
#define OT256  5120
#define OT64   5376
#define OT16   5440
#define OT4    5456
#define NTW    5460

// conflict-killing swizzle: XOR low 4 bits with bits[7:4] (self-inverse)
#define SWZ(i) ((i) ^ (((i) >> 4) & 15))

// ---------------- device scratch ----------------
__device__ float2 g_twst[NTW];
__device__ float4 g_H [(size_t)DIMD * NFFT / 2];   // spectrum of h, pass-D layout
__device__ float2 g_xt[(size_t)DIMD * DIML];       // transposed x, batches packed
__device__ float  g_ht[(size_t)DIMD * DIML];       // transposed h
__device__ float2 g_ys[(size_t)DIMD * DIML];       // transposed scaled output

__device__ __forceinline__ float2 cmul(float2 a, float2 b) {
    return make_float2(a.x * b.x - a.y * b.y, a.x * b.y + a.y * b.x);
}
__device__ __forceinline__ float2 cadd(float2 a, float2 b) { return make_float2(a.x + b.x, a.y + b.y); }
__device__ __forceinline__ float2 csub(float2 a, float2 b) { return make_float2(a.x - b.x, a.y - b.y); }

// DIF forward radix-4 butterfly (in place)
__device__ __forceinline__ void bfly(float2& a, float2& b, float2& c, float2& d) {
    float2 t0 = cadd(a, c), t1 = csub(a, c), t2 = cadd(b, d), t3 = csub(b, d);
    float2 t3s = make_float2(t3.y, -t3.x);     // -i * t3
    a = cadd(t0, t2);
    c = csub(t0, t2);
    b = cadd(t1, t3s);
    d = csub(t1, t3s);
}
// inverse radix-4 butterfly (unnormalized)
__device__ __forceinline__ void ibfly(float2& a, float2& b, float2& c, float2& d) {
    float2 u0 = cadd(a, c), u1 = csub(a, c), u2 = cadd(b, d), u3 = csub(b, d);
    float2 u3s = make_float2(u3.y, -u3.x);
    a = cadd(u0, u2);
    c = csub(u0, u2);
    b = csub(u1, u3s);
    d = cadd(u1, u3s);
}
__device__ __forceinline__ void tw3w(float2& b, float2& c, float2& d,
                                     float2 w1, float2 w2, float2 w3) {
    b = cmul(b, w1); c = cmul(c, w2); d = cmul(d, w3);
}
__device__ __forceinline__ void tw3(float2& b, float2& c, float2& d, float2 w) {
    float2 w2 = cmul(w, w), w3 = cmul(w, w2);
    tw3w(b, c, d, w, w2, w3);
}
__device__ __forceinline__ void itw3(float2& b, float2& c, float2& d, float2 w) {
    float2 wc = make_float2(w.x, -w.y);
    float2 w2 = cmul(wc, wc), w3 = cmul(wc, w2);
    tw3w(b, c, d, wc, w2, w3);
}

// ---------------- twiddle init ----------------
__global__ void twiddle_kernel() {
    const int offs[6] = {OT4096, OT1024, OT256, OT64, OT16, OT4};
    const int ms[6]   = {4096, 1024, 256, 64, 16, 4};
    int si = blockIdx.y;
    int m  = ms[si];
    int r  = blockIdx.x * 256 + threadIdx.x;
    if (r < m) {
        float s, c;
        sincospif(0.5f * (float)r / (float)m, &s, &c);
        g_twst[offs[si] + r] = make_float2(c, -s);
    }
}

// ---------------- transposes ----------------
__global__ __launch_bounds__(256)
void transpose_x_kernel(const float* __restrict__ x) {
    __shared__ float2 tile[32][33];
    const int d0 = blockIdx.x * 32, n0 = blockIdx.y * 32;
    for (int i = threadIdx.y; i < 32; i += 8) {
        const size_t base = (size_t)(n0 + i) * DIMD + d0 + threadIdx.x;
        tile[i][threadIdx.x] = make_float2(x[base], x[base + (size_t)DIML * DIMD]);
    }
    __syncthreads();
    for (int i = threadIdx.y; i < 32; i += 8)
        g_xt[(size_t)(d0 + i) * DIML + n0 + threadIdx.x] = tile[threadIdx.x][i];
}

__global__ __launch_bounds__(256)
void transpose_h_kernel(const float* __restrict__ h) {
    __shared__ float tile[32][33];
    const int d0 = blockIdx.x * 32, n0 = blockIdx.y * 32;
    for (int i = threadIdx.y; i < 32; i += 8)
        tile[i][threadIdx.x] = h[(size_t)(n0 + i) * DIMD + d0 + threadIdx.x];
    __syncthreads();
    for (int i = threadIdx.y; i < 32; i += 8)
        g_ht[(size_t)(d0 + i) * DIML + n0 + threadIdx.x] = tile[threadIdx.x][i];
}

__global__ __launch_bounds__(256)
void transpose_out_kernel(const float* __restrict__ bias, float* __restrict__ y) {
    __shared__ float2 tile[32][33];
    const int n0 = blockIdx.x * 32, d0 = blockIdx.y * 32;
    for (int i = threadIdx.y; i < 32; i += 8)
        tile[i][threadIdx.x] = g_ys[(size_t)(d0 + i) * DIML + n0 + threadIdx.x];
    __syncthreads();
    for (int i = threadIdx.y; i < 32; i += 8) {
        const int d = d0 + threadIdx.x;
        const int n = n0 + i;
        const float bv = __ldg(&bias[d]);
        const float2 v = tile[threadIdx.x][i];
        y[(size_t)n * DIMD + d]          = v.x + bv;
        y[(size_t)(DIML + n) * DIMD + d] = v.y + bv;
    }
}

// ================= pass helpers (parameterized by group index t) ============

// Pass A butterflies on v (elements t + 1024b + 4096a)
__device__ __forceinline__ void passA_fwd(float2 v[4][4], const float2* sT, int t) {
    #pragma unroll
    for (int b = 0; b < 4; b++) {
        bfly(v[0][b], v[1][b], v[2][b], v[3][b]);
        tw3(v[1][b], v[2][b], v[3][b], sT[OT4096 + t + 1024 * b]);
    }
    float2 w1 = sT[OT1024 + t];
    float2 w2 = cmul(w1, w1), w3 = cmul(w1, w2);
    #pragma unroll
    for (int a = 0; a < 4; a++) {
        bfly(v[a][0], v[a][1], v[a][2], v[a][3]);
        tw3w(v[a][1], v[a][2], v[a][3], w1, w2, w3);
    }
}

// Pass B: stages m=256, m=64. element e(a,b) = u*1024 + rp + 64b + 256a
__device__ __forceinline__ void passB_fwd(float2* sA, const float2* sT, int t) {
    const int u = t >> 6, rp = t & 63;
    const int base = u * 1024 + rp;
    float2 v[4][4];
    #pragma unroll
    for (int a = 0; a < 4; a++)
        #pragma unroll
        for (int b = 0; b < 4; b++)
            v[a][b] = sA[SWZ(base + 64 * b + 256 * a)];
    #pragma unroll
    for (int b = 0; b < 4; b++) {
        bfly(v[0][b], v[1][b], v[2][b], v[3][b]);
        tw3(v[1][b], v[2][b], v[3][b], sT[OT256 + rp + 64 * b]);
    }
    float2 w1 = sT[OT64 + rp];
    float2 w2 = cmul(w1, w1), w3 = cmul(w1, w2);
    #pragma unroll
    for (int a = 0; a < 4; a++) {
        bfly(v[a][0], v[a][1], v[a][2], v[a][3]);
        tw3w(v[a][1], v[a][2], v[a][3], w1, w2, w3);
    }
    #pragma unroll
    for (int a = 0; a < 4; a++)
        #pragma unroll
        for (int b = 0; b < 4; b++)
            sA[SWZ(base + 64 * b + 256 * a)] = v[a][b];
}

// Pass C: stage m=16. element e(s,a) = qb*64 + rq + 4096s + 16a
__device__ __forceinline__ void passC_fwd(float2* sA, const float2* sT, int t) {
    const int rq = t & 15, qb = t >> 4;
    const int base = qb * 64 + rq;
    float2 v[4][4];
    #pragma unroll
    for (int s = 0; s < 4; s++)
        #pragma unroll
        for (int a = 0; a < 4; a++)
            v[s][a] = sA[SWZ(base + 4096 * s + 16 * a)];
    float2 w1 = sT[OT16 + rq];
    float2 w2 = cmul(w1, w1), w3 = cmul(w1, w2);
    #pragma unroll
    for (int s = 0; s < 4; s++) {
        bfly(v[s][0], v[s][1], v[s][2], v[s][3]);
        tw3w(v[s][1], v[s][2], v[s][3], w1, w2, w3);
    }
    #pragma unroll
    for (int s = 0; s < 4; s++)
        #pragma unroll
        for (int a = 0; a < 4; a++)
            sA[SWZ(base + 4096 * s + 16 * a)] = v[s][a];
}

// Pass D forward: stages m=4, m=1 on u16 (elements 16t..16t+15)
__device__ __forceinline__ void passD_fwd(float2 u16[16], const float2* sT) {
    #pragma unroll
    for (int r = 0; r < 4; r++) {
        bfly(u16[r], u16[r + 4], u16[r + 8], u16[r + 12]);
        tw3(u16[r + 4], u16[r + 8], u16[r + 12], sT[OT4 + r]);
    }
    #pragma unroll
    for (int g = 0; g < 4; g++)
        bfly(u16[4 * g], u16[4 * g + 1], u16[4 * g + 2], u16[4 * g + 3]);
}

// inverse pass C' body for one group
__device__ __forceinline__ void passC_inv(float2* sA, const float2* sT, int t) {
    const int rq = t & 15, qb = t >> 4;
    const int base = qb * 64 + rq;
    float2 w1 = sT[OT16 + rq];
    w1.y = -w1.y;
    float2 w2 = cmul(w1, w1), w3 = cmul(w1, w2);
    float2 v[4][4];
    #pragma unroll
    for (int s = 0; s < 4; s++)
        #pragma unroll
        for (int a = 0; a < 4; a++)
            v[s][a] = sA[SWZ(base + 4096 * s + 16 * a)];
    #pragma unroll
    for (int s = 0; s < 4; s++) {
        tw3w(v[s][1], v[s][2], v[s][3], w1, w2, w3);
        ibfly(v[s][0], v[s][1], v[s][2], v[s][3]);
    }
    #pragma unroll
    for (int s = 0; s < 4; s++)
        #pragma unroll
        for (int a = 0; a < 4; a++)
            sA[SWZ(base + 4096 * s + 16 * a)] = v[s][a];
}

// inverse pass B' body for one group
__device__ __forceinline__ void passB_inv(float2* sA, const float2* sT, int t) {
    const int u = t >> 6, rp = t & 63;
    const int base = u * 1024 + rp;
    float2 v[4][4];
    #pragma unroll
    for (int a = 0; a < 4; a++)
        #pragma unroll
        for (int b = 0; b < 4; b++)
            v[a][b] = sA[SWZ(base + 64 * b + 256 * a)];
    float2 w1 = sT[OT64 + rp];
    w1.y = -w1.y;
    float2 w2 = cmul(w1, w1), w3 = cmul(w1, w2);
    #pragma unroll
    for (int a = 0; a < 4; a++) {
        tw3w(v[a][1], v[a][2], v[a][3], w1, w2, w3);
        ibfly(v[a][0], v[a][1], v[a][2], v[a][3]);
    }
    #pragma unroll
    for (int b = 0; b < 4; b++) {
        itw3(v[1][b], v[2][b], v[3][b], sT[OT256 + rp + 64 * b]);
        ibfly(v[0][b], v[1][b], v[2][b], v[3][b]);
    }
    #pragma unroll
    for (int a = 0; a < 4; a++)
        #pragma unroll
        for (int b = 0; b < 4; b++)
            sA[SWZ(base + 64 * b + 256 * a)] = v[a][b];
}

// ================= FFT of h: forward only, store spectrum ===================
__global__ __launch_bounds__(NT, 1)
void fft_h_kernel() {
    extern __shared__ float2 sm[];
    float2* sA = sm;
    float2* sT = sm + NFFT;
    const int tid = threadIdx.x, d = blockIdx.x;

    for (int j = tid; j < NTW; j += NT) sT[j] = g_twst[j];
    __syncthreads();                       // twiddle tables visible

    const float* hp = g_ht + (size_t)d * DIML;
    #pragma unroll
    for (int g = 0; g < 2; g++) {
        const int t = tid + 512 * g;
        float2 v[4][4];
        #pragma unroll
        for (int a = 0; a < 4; a++)
            #pragma unroll
            for (int b = 0; b < 4; b++)
                v[a][b] = (a < 2) ? make_float2(hp[t + 1024 * b + 4096 * a], 0.0f)
                                  : make_float2(0.0f, 0.0f);
        passA_fwd(v, sT, t);
        #pragma unroll
        for (int a = 0; a < 4; a++)
            #pragma unroll
            for (int b = 0; b < 4; b++)
                sA[SWZ(t + 1024 * b + 4096 * a)] = v[a][b];
    }
    __syncthreads();

    passB_fwd(sA, sT, tid);
    passB_fwd(sA, sT, tid + 512);
    __syncthreads();
    passC_fwd(sA, sT, tid);
    passC_fwd(sA, sT, tid + 512);
    __syncthreads();

    #pragma unroll
    for (int g = 0; g < 2; g++) {
        const int t = tid + 512 * g;
        float2 u16[16];
        #pragma unroll
        for (int j = 0; j < 16; j++) u16[j] = sA[SWZ(16 * t + j)];
        passD_fwd(u16, sT);
        float4* Hd = g_H + (size_t)d * (NFFT / 2) + 8 * t;
        #pragma unroll
        for (int p = 0; p < 8; p++)
            Hd[p] = make_float4(u16[2 * p].x, u16[2 * p].y,
                                u16[2 * p + 1].x, u16[2 * p + 1].y);
    }
}

// ================= conv: fwd FFT, multiply, inverse FFT =====================
__global__ __launch_bounds__(NT, 1)
void fft_conv_kernel() {
    extern __shared__ float2 sm[];
    float2* sA = sm;
    float2* sT = sm + NFFT;
    const int tid = threadIdx.x, d = blockIdx.x;

    for (int j = tid; j < NTW; j += NT) sT[j] = g_twst[j];
    __syncthreads();

    const float2* xp = g_xt + (size_t)d * DIML;
    #pragma unroll
    for (int g = 0; g < 2; g++) {
        const int t = tid + 512 * g;
        float2 v[4][4];
        #pragma unroll
        for (int a = 0; a < 4; a++)
            #pragma unroll
            for (int b = 0; b < 4; b++)
                v[a][b] = (a < 2) ? xp[t + 1024 * b + 4096 * a] : make_float2(0.0f, 0.0f);
        passA_fwd(v, sT, t);
        #pragma unroll
        for (int a = 0; a < 4; a++)
            #pragma unroll
            for (int b = 0; b < 4; b++)
                sA[SWZ(t + 1024 * b + 4096 * a)] = v[a][b];
    }
    __syncthreads();

    passB_fwd(sA, sT, tid);
    passB_fwd(sA, sT, tid + 512);
    __syncthreads();
    passC_fwd(sA, sT, tid);
    passC_fwd(sA, sT, tid + 512);
    __syncthreads();

    // ---- pass D: fwd(4,1) + multiply by H + inv(1,4), in registers ----
    #pragma unroll
    for (int g = 0; g < 2; g++) {
        const int t = tid + 512 * g;
        float2 u16[16];
        #pragma unroll
        for (int j = 0; j < 16; j++) u16[j] = sA[SWZ(16 * t + j)];
        passD_fwd(u16, sT);

        const float4* Hd = g_H + (size_t)d * (NFFT / 2) + 8 * t;
        #pragma unroll
        for (int p = 0; p < 8; p++) {
            float4 hv = __ldg(&Hd[p]);
            u16[2 * p]     = cmul(u16[2 * p],     make_float2(hv.x, hv.y));
            u16[2 * p + 1] = cmul(u16[2 * p + 1], make_float2(hv.z, hv.w));
        }

        #pragma unroll
        for (int q = 0; q < 4; q++)
            ibfly(u16[4 * q], u16[4 * q + 1], u16[4 * q + 2], u16[4 * q + 3]);
        #pragma unroll
        for (int r = 0; r < 4; r++) {
            itw3(u16[r + 4], u16[r + 8], u16[r + 12], sT[OT4 + r]);
            ibfly(u16[r], u16[r + 4], u16[r + 8], u16[r + 12]);
        }
        #pragma unroll
        for (int j = 0; j < 16; j++) sA[SWZ(16 * t + j)] = u16[j];
    }
    __syncthreads();

    passC_inv(sA, sT, tid);
    passC_inv(sA, sT, tid + 512);
    __syncthreads();
    passB_inv(sA, sT, tid);
    passB_inv(sA, sT, tid + 512);
    __syncthreads();

    // ---- pass A': inverse stages 1024 then 4096, scale + store ----
    const float scale = 1.0f / (float)NFFT;
    float2* yp = g_ys + (size_t)d * DIML;
    #pragma unroll
    for (int g = 0; g < 2; g++) {
        const int t = tid + 512 * g;
        float2 v[4][4];
        #pragma unroll
        for (int a = 0; a < 4; a++)
            #pragma unroll
            for (int b = 0; b < 4; b++)
                v[a][b] = sA[SWZ(t + 1024 * b + 4096 * a)];
        float2 w1 = sT[OT1024 + t];
        w1.y = -w1.y;
        float2 w2 = cmul(w1, w1), w3 = cmul(w1, w2);
        #pragma unroll
        for (int a = 0; a < 4; a++) {
            tw3w(v[a][1], v[a][2], v[a][3], w1, w2, w3);
            ibfly(v[a][0], v[a][1], v[a][2], v[a][3]);
        }
        #pragma unroll
        for (int b = 0; b < 4; b++) {
            itw3(v[1][b], v[2][b], v[3][b], sT[OT4096 + t + 1024 * b]);
            ibfly(v[0][b], v[1][b], v[2][b], v[3][b]);
        }
        #pragma unroll
        for (int a = 0; a < 2; a++)
            #pragma unroll
            for (int b = 0; b < 4; b++) {
                float2 r = v[a][b];
                yp[t + 1024 * b + 4096 * a] = make_float2(r.x * scale, r.y * scale);
            }
    }
}

// ---------------------------------------------------------------------------
extern "C" void kernel_launch(void* const* d_in, const int* in_sizes, int n_in,
                              void* d_out, int out_size) {
    const float* x    = (const float*)d_in[0];
    const float* h    = (const float*)d_in[1];
    const float* bias = (const float*)d_in[2];
    float* y = (float*)d_out;

    const int smem = (NFFT + NTW) * sizeof(float2);  // ~171 KB
    cudaFuncSetAttribute(fft_h_kernel,
                         cudaFuncAttributeMaxDynamicSharedMemorySize, smem);
    cudaFuncSetAttribute(fft_conv_kernel,
                         cudaFuncAttributeMaxDynamicSharedMemorySize, smem);

    twiddle_kernel<<<dim3(16, 6), 256>>>();
    transpose_x_kernel<<<dim3(DIMD / 32, DIML / 32), dim3(32, 8)>>>(x);
    transpose_h_kernel<<<dim3(DIMD / 32, DIML / 32), dim3(32, 8)>>>(h);
    fft_h_kernel<<<DIMD, NT, smem>>>();
    fft_conv_kernel<<<DIMD, NT, smem>>>();
    transpose_out_kernel<<<dim3(DIML / 32, DIMD / 32), dim3(32, 8)>>>(bias, y);
}